// round 10
// baseline (speedup 1.0000x reference)
#include <cuda_runtime.h>
#include <cuda_bf16.h>

// TemporalConsistencyLoss — batch-fixed blocks, register-resident row data.
//
// R10 vs R9 (35.3us, DRAM 56.5%/issue 43%/occ 73%):
//  - __ldcs evict-first on all streaming (read-once) loads.
//  - software pipeline depth 2 on the pc/tc streams (4 LDG.128 in flight).
//  - precompute c = 0.5 + ptj per lane (ordering hinge: relu(c - pti)).
//  - otherwise identical structure: 444 blocks x 512 thr = 148 SMs x 3 CTAs,
//    phase A ordering+BCE batch-fixed, phase B transitivity on prec[0],
//    per-block partials + ticket finalize (graph-replay safe).

#define S_DIM 2048
#define B_DIM 4
#define SS (S_DIM * S_DIM)              // 2^22
#define NTOT (B_DIM * SS)               // 2^24
#define NTHR 512
#define NBLK 444                        // 148 SMs * 3 CTAs
#define BLK_PER_B 111                   // NBLK / B_DIM

__device__ double g_part[NBLK][3];
__device__ unsigned int g_ticket;       // zero at module load; reset by last block

// ordering + BCE for one float4 group (all scalars). c = 0.5 + ptj.
__device__ __forceinline__ void main_math(
    float4 p4, int4 t4, float4 c, float4 ttj, float pti, float tti,
    float& ord, float& bce)
{
    // BCE: log of product -> 1 MUFU per 4 elements (clamp preserved ~2e-7 rel)
    float v0 = t4.x ? p4.x : (1.0f - p4.x);
    float v1 = t4.y ? p4.y : (1.0f - p4.y);
    float v2 = t4.z ? p4.z : (1.0f - p4.z);
    float v3 = t4.w ? p4.w : (1.0f - p4.w);
    bce -= fmaxf(__logf((v0 * v1) * (v2 * v3)), -100.0f);

    // ordering hinge: torder ? relu((0.5+ptj) - pti) : 0.5
    ord += (tti < ttj.x) ? fmaxf(c.x - pti, 0.0f) : 0.5f;
    ord += (tti < ttj.y) ? fmaxf(c.y - pti, 0.0f) : 0.5f;
    ord += (tti < ttj.z) ? fmaxf(c.z - pti, 0.0f) : 0.5f;
    ord += (tti < ttj.w) ? fmaxf(c.w - pti, 0.0f) : 0.5f;
}

// transitivity for one float4 group (accumulates w*s; /4 folded into finalize)
__device__ __forceinline__ void trans_math(
    int j, int i, int4 pr,
    float4 q0, float4 q1, float4 q2, float4 q3,
    float i0, float i1, float i2, float i3,
    float& tr)
{
    int g; float w, s;
    g = j - i;
    w = (g >= 2 && pr.x != 0) ? (float)(g - 1) : 0.0f;
    s = fmaxf(0.1f - (q0.x - i0), 0.0f) + fmaxf(0.1f - (q1.x - i1), 0.0f)
      + fmaxf(0.1f - (q2.x - i2), 0.0f) + fmaxf(0.1f - (q3.x - i3), 0.0f);
    tr += w * s;
    g = j + 1 - i;
    w = (g >= 2 && pr.y != 0) ? (float)(g - 1) : 0.0f;
    s = fmaxf(0.1f - (q0.y - i0), 0.0f) + fmaxf(0.1f - (q1.y - i1), 0.0f)
      + fmaxf(0.1f - (q2.y - i2), 0.0f) + fmaxf(0.1f - (q3.y - i3), 0.0f);
    tr += w * s;
    g = j + 2 - i;
    w = (g >= 2 && pr.z != 0) ? (float)(g - 1) : 0.0f;
    s = fmaxf(0.1f - (q0.z - i0), 0.0f) + fmaxf(0.1f - (q1.z - i1), 0.0f)
      + fmaxf(0.1f - (q2.z - i2), 0.0f) + fmaxf(0.1f - (q3.z - i3), 0.0f);
    tr += w * s;
    g = j + 3 - i;
    w = (g >= 2 && pr.w != 0) ? (float)(g - 1) : 0.0f;
    s = fmaxf(0.1f - (q0.w - i0), 0.0f) + fmaxf(0.1f - (q1.w - i1), 0.0f)
      + fmaxf(0.1f - (q2.w - i2), 0.0f) + fmaxf(0.1f - (q3.w - i3), 0.0f);
    tr += w * s;
}

__global__ void __launch_bounds__(NTHR, 3) tcl_fused_kernel(
    const float* __restrict__ pred_times,
    const float* __restrict__ pred_causal,
    const float* __restrict__ target_times,
    const int*   __restrict__ target_causal,
    const int*   __restrict__ target_prec,
    float* __restrict__ out, int out_size)
{
    const int tid = threadIdx.x;
    const int bid = blockIdx.x;
    float ord = 0.0f, bce = 0.0f, tr = 0.0f;

    // ================= PHASE A: ordering + BCE (batch fixed) ================
    {
        const int b = bid / BLK_PER_B;       // 0..3, constant per block (UR)
        const int k = bid - b * BLK_PER_B;   // 0..110

        // loop-invariant: this thread's column chunk of pt/tt for batch b
        const float4* __restrict__ pt4 = reinterpret_cast<const float4*>(pred_times)   + (b << 9);
        const float4* __restrict__ tt4 = reinterpret_cast<const float4*>(target_times) + (b << 9);
        const float4 ptj = __ldg(pt4 + tid);
        const float4 ttj = __ldg(tt4 + tid);
        const float4 c = make_float4(0.5f + ptj.x, 0.5f + ptj.y,
                                     0.5f + ptj.z, 0.5f + ptj.w);

        const float* __restrict__ ptrow = pred_times + (b << 11);
        const float* __restrict__ ttrow = target_times + (b << 11);
        const float4* __restrict__ pc4 = reinterpret_cast<const float4*>(pred_causal)  + (b << 20);
        const int4*   __restrict__ tc4 = reinterpret_cast<const int4*>(target_causal)  + (b << 20);

        // depth-2 software pipeline over rows k, k+111, ... (<2048)
        int   r0 = k;
        int   r1 = k + BLK_PER_B;
        float4 p0 = __ldcs(pc4 + (r0 << 9) + tid);
        int4   t0 = __ldcs(tc4 + (r0 << 9) + tid);
        bool  has1 = r1 < S_DIM;
        float4 p1; int4 t1;
        if (has1) {
            p1 = __ldcs(pc4 + (r1 << 9) + tid);
            t1 = __ldcs(tc4 + (r1 << 9) + tid);
        }

        #pragma unroll 1
        for (;;) {
            const int r2 = r1 + BLK_PER_B;
            const bool has2 = has1 && (r2 < S_DIM);
            float4 p2; int4 t2;
            if (has2) {
                p2 = __ldcs(pc4 + (r2 << 9) + tid);
                t2 = __ldcs(tc4 + (r2 << 9) + tid);
            }
            const float pti = __ldg(ptrow + r0);
            const float tti = __ldg(ttrow + r0);
            main_math(p0, t0, c, ttj, pti, tti, ord, bce);
            if (!has1) break;
            p0 = p1; t0 = t1; r0 = r1;
            p1 = p2; t1 = t2; r1 = r2; has1 = has2;
        }
    }

    // ================= PHASE B: transitivity on prec[0] =====================
    {
        const float4* __restrict__ q4 = reinterpret_cast<const float4*>(pred_times);
        const float4 q0 = __ldg(q4 + tid);              // batch 0 row chunk
        const float4 q1 = __ldg(q4 + 512 + tid);
        const float4 q2 = __ldg(q4 + 1024 + tid);
        const float4 q3 = __ldg(q4 + 1536 + tid);
        const int4* __restrict__ pr4 = reinterpret_cast<const int4*>(target_prec);
        const int j = tid << 2;

        #pragma unroll 1
        for (int i = bid; i < S_DIM; i += NBLK) {
            const int4 pr = __ldcs(pr4 + (i << 9) + tid);
            const float i0 = __ldg(pred_times + i);
            const float i1 = __ldg(pred_times + S_DIM + i);
            const float i2 = __ldg(pred_times + 2 * S_DIM + i);
            const float i3 = __ldg(pred_times + 3 * S_DIM + i);
            trans_math(j, i, pr, q0, q1, q2, q3, i0, i1, i2, i3, tr);
        }
    }

    // ---- block reduction in double ----
    __shared__ double sh0[NTHR];
    __shared__ double sh1[NTHR];
    __shared__ double sh2[NTHR];
    sh0[tid] = (double)ord;
    sh1[tid] = (double)bce;
    sh2[tid] = (double)tr;
    __syncthreads();
    #pragma unroll
    for (int off = NTHR / 2; off > 0; off >>= 1) {
        if (tid < off) {
            sh0[tid] += sh0[tid + off];
            sh1[tid] += sh1[tid + off];
            sh2[tid] += sh2[tid + off];
        }
        __syncthreads();
    }

    // ---- write partial + ticket; dynamically-last block finalizes ----
    __shared__ bool s_is_last;
    if (tid == 0) {
        g_part[bid][0] = sh0[0];
        g_part[bid][1] = sh1[0];
        g_part[bid][2] = sh2[0];
        __threadfence();
        unsigned int t = atomicAdd(&g_ticket, 1u);
        s_is_last = (t == (unsigned)(NBLK - 1));
    }
    __syncthreads();

    if (s_is_last) {
        double a0 = 0.0, a1 = 0.0, a2 = 0.0;
        for (int k2 = tid; k2 < NBLK; k2 += NTHR) {
            a0 += g_part[k2][0];
            a1 += g_part[k2][1];
            a2 += g_part[k2][2];
        }
        sh0[tid] = a0; sh1[tid] = a1; sh2[tid] = a2;
        __syncthreads();
        #pragma unroll
        for (int off = NTHR / 2; off > 0; off >>= 1) {
            if (tid < off) {
                sh0[tid] += sh0[tid + off];
                sh1[tid] += sh1[tid + off];
                sh2[tid] += sh2[tid + off];
            }
            __syncthreads();
        }
        if (tid == 0) {
            const double N = (double)NTOT;
            double ordering  = sh0[0] / N;
            double causality = sh1[0] / N;
            const double denom = (double)S_DIM * (S_DIM - 1) * (S_DIM - 2) / 6.0;
            double transitivity = (sh2[0] * 0.25) / denom;   // mean over B=4
            double total = ordering + 0.8 * causality + 0.6 * transitivity;
            if (out_size >= 4) {
                out[0] = (float)ordering;
                out[1] = (float)causality;
                out[2] = (float)transitivity;
                out[3] = (float)total;
            } else {
                out[0] = (float)total;
            }
            __threadfence();
            g_ticket = 0;   // reset for next graph replay
        }
    }
}

extern "C" void kernel_launch(void* const* d_in, const int* in_sizes, int n_in,
                              void* d_out, int out_size) {
    const float* pred_times    = (const float*)d_in[0];
    const float* pred_causal   = (const float*)d_in[1];
    const float* target_times  = (const float*)d_in[2];
    const int*   target_causal = (const int*)d_in[3];
    const int*   target_prec   = (const int*)d_in[4];
    float* out = (float*)d_out;

    tcl_fused_kernel<<<NBLK, NTHR>>>(pred_times, pred_causal, target_times,
                                     target_causal, target_prec, out, out_size);
}